// round 10
// baseline (speedup 1.0000x reference)
#include <cuda_runtime.h>

// ---------------------------------------------------------------------------
// LieSpline: SE(3) cubic B-spline interpolation.  B=32, N=2048, K=32.
//
// Kernel 1: per padded delta j (0..N): se3_log(inv(P[j])P[j+1]) + lane-
//   invariant exp precomputes + base pose, packed 5 float4 (80B) per record:
//     r0 = (tau.xyz | nd)
//     r1 = (U.xyz   | C1'.x)      C1' = (2/nd^2) * cross(phi,tau)
//     r2 = (C1'.y, C1'.z, C2'.x, C2'.y)  C2' = (1/nd^3)*cross(phi,cross(phi,tau))
//     r3 = (C2'.z, pose_t.xyz)
//     r4 = pose_q
// Kernel 2: warp = (b, 4 consecutive segments), lane = time sample (K==32).
//   6 records (30 contiguous float4) cooperatively loaded by lanes 0..29 into
//   smem in ONE LDG.128; then 4 interleaved compose chains (4-way ILP),
//   record-serial consumption so each record is read from smem once.
// ---------------------------------------------------------------------------

#define LS_B 32
#define LS_N 2048
#define LS_J (LS_N + 1)   // 2049 deltas per batch
#define REC 5             // float4s per delta record
#define LS_S (LS_N - 1)   // 2047 segments
#define LS_M 512          // segment-quads per batch (ceil(2047/4))

__device__ float4 g_pre[LS_B * LS_J * REC];   // 5.2 MB scratch

__device__ __forceinline__ float3 f3(float x, float y, float z) {
    return make_float3(x, y, z);
}
__device__ __forceinline__ float3 cross3(const float3 a, const float3 b) {
    return make_float3(a.y * b.z - a.z * b.y,
                       a.z * b.x - a.x * b.z,
                       a.x * b.y - a.y * b.x);
}
__device__ __forceinline__ float dot3(const float3 a, const float3 b) {
    return a.x * b.x + a.y * b.y + a.z * b.z;
}
__device__ __forceinline__ float3 qrot(const float4 q, const float3 v) {
    float3 qv = f3(q.x, q.y, q.z);
    float3 t = cross3(qv, v);
    t.x *= 2.0f; t.y *= 2.0f; t.z *= 2.0f;
    float3 c = cross3(qv, t);
    return f3(v.x + q.w * t.x + c.x,
              v.y + q.w * t.y + c.y,
              v.z + q.w * t.z + c.z);
}
__device__ __forceinline__ float4 qmul(const float4 a, const float4 b) {
    return make_float4(
        a.w * b.x + a.x * b.w + a.y * b.z - a.z * b.y,
        a.w * b.y + a.y * b.w + a.z * b.x - a.x * b.z,
        a.w * b.z + a.z * b.w + a.x * b.y - a.y * b.x,
        a.w * b.w - a.x * b.x - a.y * b.y - a.z * b.z);
}

// ---------------------------------------------------------------------------
// Kernel 1: per-(b, j) relative-pose log + precompute
// ---------------------------------------------------------------------------
__global__ void __launch_bounds__(128) k_delta(const float* __restrict__ poses) {
    unsigned idx = blockIdx.x * blockDim.x + threadIdx.x;
    if (idx >= LS_B * LS_J) return;
    unsigned b = idx / LS_J;
    unsigned j = idx - b * LS_J;
    float4* o = g_pre + idx * REC;
    const float* pbase = poses + b * (LS_N * 7);

    unsigned pj = j > 0 ? j - 1 : 0;
    const float* pr = pbase + pj * 7;
    float3 t0 = f3(pr[0], pr[1], pr[2]);
    float4 q0 = make_float4(pr[3], pr[4], pr[5], pr[6]);
    o[4] = q0;

    if (j == 0 || j == LS_N) {
        float4 z = make_float4(0.f, 0.f, 0.f, 0.f);
        o[0] = z; o[1] = z; o[2] = z;
        o[3] = make_float4(0.f, t0.x, t0.y, t0.z);
        return;
    }
    const float* pr1 = pr + 7;
    float3 t1 = f3(pr1[0], pr1[1], pr1[2]);
    float4 q1 = make_float4(pr1[3], pr1[4], pr1[5], pr1[6]);

    float4 qi = make_float4(-q0.x, -q0.y, -q0.z, q0.w);
    float3 dt = f3(t1.x - t0.x, t1.y - t0.y, t1.z - t0.z);
    float3 t  = qrot(qi, dt);
    float4 q  = qmul(qi, q1);

    float n2 = q.x * q.x + q.y * q.y + q.z * q.z;
    bool small = n2 < 1e-12f;
    float ns = small ? 1.0f : n2;
    float rn = rsqrtf(ns);
    float n  = ns * rn;
    float factor;
    if (small) {
        float iw = __fdividef(1.0f, q.w);
        factor = 2.0f * iw - (2.0f / 3.0f) * n2 * iw * iw * iw;
    } else {
        factor = 2.0f * atan2f(n, q.w) * rn;
    }
    float3 phi = f3(factor * q.x, factor * q.y, factor * q.z);

    float t2 = dot3(phi, phi);
    bool sm2 = t2 < 1e-12f;
    float t2s = sm2 ? 1.0f : t2;
    float rth = rsqrtf(t2s);
    float theta = t2s * rth;
    float s, cth;
    __sincosf(theta, &s, &cth);
    float s_safe = (fabsf(s) < 1e-6f) ? 1e-6f : s;
    float c;
    if (sm2) {
        c = (1.0f / 12.0f) + t2 * (1.0f / 720.0f);
    } else {
        c = rth * rth - __fdividef(1.0f + cth, 2.0f * theta * s_safe);
    }
    float3 x1 = cross3(phi, t);
    float3 x2 = cross3(phi, x1);
    float3 tau = f3(t.x - 0.5f * x1.x + c * x2.x,
                    t.y - 0.5f * x1.y + c * x2.y,
                    t.z - 0.5f * x1.z + c * x2.z);

    float nd2 = dot3(phi, phi);
    if (nd2 < 1e-24f) {
        o[0] = make_float4(tau.x, tau.y, tau.z, 0.f);
        o[1] = make_float4(0.f, 0.f, 0.f, 0.f);
        o[2] = make_float4(0.f, 0.f, 0.f, 0.f);
        o[3] = make_float4(0.f, t0.x, t0.y, t0.z);
        return;
    }
    float rnd = rsqrtf(nd2);         // 1/nd
    float nd  = nd2 * rnd;           // |phi|
    float K2  = 2.0f * rnd * rnd;    // 2/nd^2
    float rn3 = rnd * rnd * rnd;     // 1/nd^3
    float3 U  = f3(phi.x * rnd, phi.y * rnd, phi.z * rnd);
    float3 C1 = cross3(phi, tau);
    float3 C2 = cross3(phi, C1);
    C1.x *= K2;  C1.y *= K2;  C1.z *= K2;    // C1'
    C2.x *= rn3; C2.y *= rn3; C2.z *= rn3;   // C2'
    o[0] = make_float4(tau.x, tau.y, tau.z, nd);
    o[1] = make_float4(U.x, U.y, U.z, C1.x);
    o[2] = make_float4(C1.y, C1.z, C2.x, C2.y);
    o[3] = make_float4(C2.z, t0.x, t0.y, t0.z);
}

// ---------------------------------------------------------------------------
// exp + in-place right-compose: T <- T * exp(wk * delta)
// record fields: r0 = tau|nd, r1 = U|C1'x, r2 = C1'yz C2'xy, c2z = C2'z
// ---------------------------------------------------------------------------
struct Xf { float3 t; float4 q; };

__device__ __forceinline__ void stepc(Xf& T,
                                      const float4 r0, const float4 r1,
                                      const float4 r2, float c2z,
                                      float wk) {
    float theta = wk * r0.w;
    float sh, ch;
    __sincosf(0.5f * theta, &sh, &ch);
    float alpha = sh * sh;                        // (1 - cos th) with K2 premult
    float beta  = fmaf(-(sh + sh), ch, theta);    // th - sin th  with rn3 premult
    float3 At;
    At.x = fmaf(beta, r2.z, fmaf(alpha, r1.w, wk * r0.x));
    At.y = fmaf(beta, r2.w, fmaf(alpha, r2.x, wk * r0.y));
    At.z = fmaf(beta, c2z,  fmaf(alpha, r2.y, wk * r0.z));
    float4 Aq = make_float4(sh * r1.x, sh * r1.y, sh * r1.z, ch);
    float3 r = qrot(T.q, At);
    T.t.x += r.x; T.t.y += r.y; T.t.z += r.z;
    T.q = qmul(T.q, Aq);
}

// ---------------------------------------------------------------------------
// Kernel 2: warp = (b, quad m -> segments 4m..4m+3), lane = sample k.
// ---------------------------------------------------------------------------
__global__ void __launch_bounds__(256) k_spline(const float* __restrict__ timev,
                                                float* __restrict__ out) {
    __shared__ __align__(16) float4 recbuf[8 * 30];   // 6 records/warp
    __shared__ __align__(16) float  stg[8 * 896];     // 4 * 224 floats/warp

    unsigned w    = threadIdx.x >> 5;
    unsigned lane = threadIdx.x & 31;
    unsigned gp = blockIdx.x * 8 + w;
    if (gp >= LS_B * LS_M) return;
    unsigned b = gp >> 9;            // / LS_M
    unsigned m = gp & (LS_M - 1);
    unsigned s0 = 4 * m;
    unsigned nvalid = LS_S - s0;      // segments valid from s0
    if (nvalid > 4) nvalid = 4;       // 4 normally, 3 on the tail quad

    // ---- cooperative record load: 30 contiguous float4 (records s0..s0+5)
    {
        unsigned gbase = (b * LS_J + s0) * REC;
        const unsigned GMAX = LS_B * LS_J * REC - 1;
        unsigned gidx = gbase + lane;
        if (gidx > GMAX) gidx = GMAX;       // tail clamp (loaded but unused)
        if (lane < 30) recbuf[w * 30 + lane] = g_pre[gidx];
    }
    __syncwarp();

    float u  = __ldg(timev + lane);
    float u2 = u * u;
    float u3 = u2 * u;
    const float w0 = (5.0f + 3.0f * u - 3.0f * u2 + u3) * (1.0f / 6.0f);
    const float w1 = (1.0f + 3.0f * u + 3.0f * u2 - 2.0f * u3) * (1.0f / 6.0f);
    const float w2 = u3 * (1.0f / 6.0f);

    const float4* R = recbuf + w * 30;   // warp-uniform smem

    Xf T0, T1, T2, T3;
    // rec 0: start T0
    {
        float4 r0 = R[0], r1 = R[1], r2 = R[2], r3 = R[3], r4 = R[4];
        T0.t = f3(r3.y, r3.z, r3.w);  T0.q = r4;
        stepc(T0, r0, r1, r2, r3.x, w0);
    }
    // rec 1: start T1; advance T0
    {
        const float4* Rr = R + 5;
        float4 r0 = Rr[0], r1 = Rr[1], r2 = Rr[2], r3 = Rr[3], r4 = Rr[4];
        T1.t = f3(r3.y, r3.z, r3.w);  T1.q = r4;
        stepc(T1, r0, r1, r2, r3.x, w0);
        stepc(T0, r0, r1, r2, r3.x, w1);
    }
    // rec 2: start T2; advance T1; finish T0
    {
        const float4* Rr = R + 10;
        float4 r0 = Rr[0], r1 = Rr[1], r2 = Rr[2], r3 = Rr[3], r4 = Rr[4];
        T2.t = f3(r3.y, r3.z, r3.w);  T2.q = r4;
        stepc(T2, r0, r1, r2, r3.x, w0);
        stepc(T1, r0, r1, r2, r3.x, w1);
        stepc(T0, r0, r1, r2, r3.x, w2);
    }
    // rec 3: start T3; advance T2; finish T1
    {
        const float4* Rr = R + 15;
        float4 r0 = Rr[0], r1 = Rr[1], r2 = Rr[2], r3 = Rr[3], r4 = Rr[4];
        T3.t = f3(r3.y, r3.z, r3.w);  T3.q = r4;
        stepc(T3, r0, r1, r2, r3.x, w0);
        stepc(T2, r0, r1, r2, r3.x, w1);
        stepc(T1, r0, r1, r2, r3.x, w2);
    }
    // rec 4: advance T3; finish T2
    {
        const float4* Rr = R + 20;
        float4 r0 = Rr[0], r1 = Rr[1], r2 = Rr[2];
        float c2z = Rr[3].x;
        stepc(T3, r0, r1, r2, c2z, w1);
        stepc(T2, r0, r1, r2, c2z, w2);
    }
    // rec 5: finish T3
    {
        const float4* Rr = R + 25;
        float4 r0 = Rr[0], r1 = Rr[1], r2 = Rr[2];
        float c2z = Rr[3].x;
        stepc(T3, r0, r1, r2, c2z, w2);
    }

    // stage through shared; 896 contiguous floats per warp
    float* smw = stg + w * 896;
    unsigned o7 = lane * 7;
    {
        float* p = smw + o7;
        p[0] = T0.t.x; p[1] = T0.t.y; p[2] = T0.t.z;
        p[3] = T0.q.x; p[4] = T0.q.y; p[5] = T0.q.z; p[6] = T0.q.w;
        p += 224;
        p[0] = T1.t.x; p[1] = T1.t.y; p[2] = T1.t.z;
        p[3] = T1.q.x; p[4] = T1.q.y; p[5] = T1.q.z; p[6] = T1.q.w;
        p += 224;
        p[0] = T2.t.x; p[1] = T2.t.y; p[2] = T2.t.z;
        p[3] = T2.q.x; p[4] = T2.q.y; p[5] = T2.q.z; p[6] = T2.q.w;
        p += 224;
        p[0] = T3.t.x; p[1] = T3.t.y; p[2] = T3.t.z;
        p[3] = T3.q.x; p[4] = T3.q.y; p[5] = T3.q.z; p[6] = T3.q.w;
    }
    __syncwarp();

    const float4* sm4 = (const float4*)smw;
    unsigned pair0 = b * LS_S + s0;
    float4* ob4 = (float4*)(out) + pair0 * 56;   // 224 floats = 56 float4
    unsigned nf4 = nvalid * 56;                  // 224 (full) or 168 (tail)
#pragma unroll 7
    for (unsigned i = lane; i < nf4; i += 32)
        ob4[i] = sm4[i];
}

extern "C" void kernel_launch(void* const* d_in, const int* in_sizes, int n_in,
                              void* d_out, int out_size) {
    (void)n_in; (void)out_size;
    const float* poses = (const float*)d_in[0];
    const float* timev = (const float*)d_in[1];
    float* out = (float*)d_out;

    int tot1 = LS_B * LS_J;
    k_delta<<<(tot1 + 127) / 128, 128>>>(poses);

    int tot2 = LS_B * LS_M;   // 16384 warps
    k_spline<<<(tot2 + 7) / 8, 256>>>(timev, out);
}

// round 11
// speedup vs baseline: 1.0089x; 1.0089x over previous
#include <cuda_runtime.h>

// ---------------------------------------------------------------------------
// LieSpline: SE(3) cubic B-spline interpolation.  B=32, N=2048, K=32.  FUSED.
//
// Block = 8 warps = 32 consecutive segments of one batch (grid 64 x 32).
// Phase 1: threads 0..33 (two warps, parallel) compute the 34 delta records
//   the block needs into shared memory, 5 float4 each:
//     r0 = (tau.xyz | nd)
//     r1 = (U.xyz   | C1'.x)      C1' = (2/nd^2) * cross(phi,tau)
//     r2 = (C1'.y, C1'.z, C2'.x, C2'.y)  C2' = (1/nd^3)*cross(phi,cross(phi,tau))
//     r3 = (C2'.z, pose_t.xyz)
//     r4 = pose_q
//   Records with j > N are zero-filled (zero record => identity transform).
// Phase 2 (R10-proven): warp w handles segments s_base+4w .. +3, lane = time
//   sample.  4 interleaved compose chains, record-serial smem consumption,
//   coalesced float4 output via shared staging.
// ---------------------------------------------------------------------------

#define LS_B 32
#define LS_N 2048
#define LS_S (LS_N - 1)      // 2047 segments
#define SEG_PER_BLK 32
#define BLK_PER_B 64         // 64 * 32 = 2048 >= 2047
#define NRECB 34             // records s_base .. s_base+33

__device__ __forceinline__ float3 f3(float x, float y, float z) {
    return make_float3(x, y, z);
}
__device__ __forceinline__ float3 cross3(const float3 a, const float3 b) {
    return make_float3(a.y * b.z - a.z * b.y,
                       a.z * b.x - a.x * b.z,
                       a.x * b.y - a.y * b.x);
}
__device__ __forceinline__ float dot3(const float3 a, const float3 b) {
    return a.x * b.x + a.y * b.y + a.z * b.z;
}
__device__ __forceinline__ float3 qrot(const float4 q, const float3 v) {
    float3 qv = f3(q.x, q.y, q.z);
    float3 t = cross3(qv, v);
    t.x *= 2.0f; t.y *= 2.0f; t.z *= 2.0f;
    float3 c = cross3(qv, t);
    return f3(v.x + q.w * t.x + c.x,
              v.y + q.w * t.y + c.y,
              v.z + q.w * t.z + c.z);
}
__device__ __forceinline__ float4 qmul(const float4 a, const float4 b) {
    return make_float4(
        a.w * b.x + a.x * b.w + a.y * b.z - a.z * b.y,
        a.w * b.y + a.y * b.w + a.z * b.x - a.x * b.z,
        a.w * b.z + a.z * b.w + a.x * b.y - a.y * b.x,
        a.w * b.w - a.x * b.x - a.y * b.y - a.z * b.z);
}

struct Xf { float3 t; float4 q; };

// exp + in-place right-compose: T <- T * exp(wk * delta)
// record fields: r0 = tau|nd, r1 = U|C1'x, r2 = C1'yz C2'xy, c2z = C2'z
__device__ __forceinline__ void stepc(Xf& T,
                                      const float4 r0, const float4 r1,
                                      const float4 r2, float c2z,
                                      float wk) {
    float theta = wk * r0.w;
    float sh, ch;
    __sincosf(0.5f * theta, &sh, &ch);
    float alpha = sh * sh;                        // (1 - cos th) with K2 premult
    float beta  = fmaf(-(sh + sh), ch, theta);    // th - sin th  with rn3 premult
    float3 At;
    At.x = fmaf(beta, r2.z, fmaf(alpha, r1.w, wk * r0.x));
    At.y = fmaf(beta, r2.w, fmaf(alpha, r2.x, wk * r0.y));
    At.z = fmaf(beta, c2z,  fmaf(alpha, r2.y, wk * r0.z));
    float4 Aq = make_float4(sh * r1.x, sh * r1.y, sh * r1.z, ch);
    float3 r = qrot(T.q, At);
    T.t.x += r.x; T.t.y += r.y; T.t.z += r.z;
    T.q = qmul(T.q, Aq);
}

// ---------------------------------------------------------------------------
__global__ void __launch_bounds__(256, 4)
k_fused(const float* __restrict__ poses,
        const float* __restrict__ timev,
        float* __restrict__ out) {
    __shared__ __align__(16) float4 rec[NRECB * 5];     // 2720 B
    __shared__ __align__(16) float  stg[8 * 896];       // 28672 B

    const unsigned b      = blockIdx.y;
    const unsigned s_base = blockIdx.x * SEG_PER_BLK;
    const unsigned tid    = threadIdx.x;
    const float* pbase = poses + b * (LS_N * 7);

    // ---------------- Phase 1: 34 delta records (threads 0..33) -------------
    if (tid < NRECB) {
        float4* o = rec + tid * 5;
        unsigned j = s_base + tid;           // delta index
        if (j > LS_N) {
            // out-of-range record: all zero (exp = identity, pose unused)
            float4 z = make_float4(0.f, 0.f, 0.f, 0.f);
            o[0] = z; o[1] = z; o[2] = z; o[3] = z; o[4] = z;
        } else {
            unsigned pj = j > 0 ? j - 1 : 0;
            const float* pr = pbase + pj * 7;
            float3 t0 = f3(pr[0], pr[1], pr[2]);
            float4 q0 = make_float4(pr[3], pr[4], pr[5], pr[6]);
            o[4] = q0;
            if (j == 0 || j == LS_N) {
                float4 z = make_float4(0.f, 0.f, 0.f, 0.f);
                o[0] = z; o[1] = z; o[2] = z;
                o[3] = make_float4(0.f, t0.x, t0.y, t0.z);
            } else {
                const float* pr1 = pr + 7;
                float3 t1 = f3(pr1[0], pr1[1], pr1[2]);
                float4 q1 = make_float4(pr1[3], pr1[4], pr1[5], pr1[6]);

                float4 qi = make_float4(-q0.x, -q0.y, -q0.z, q0.w);
                float3 dt = f3(t1.x - t0.x, t1.y - t0.y, t1.z - t0.z);
                float3 t  = qrot(qi, dt);
                float4 q  = qmul(qi, q1);

                // so3_log
                float n2 = q.x * q.x + q.y * q.y + q.z * q.z;
                bool small = n2 < 1e-12f;
                float ns = small ? 1.0f : n2;
                float rn = rsqrtf(ns);
                float n  = ns * rn;
                float factor;
                if (small) {
                    float iw = __fdividef(1.0f, q.w);
                    factor = 2.0f * iw - (2.0f / 3.0f) * n2 * iw * iw * iw;
                } else {
                    factor = 2.0f * atan2f(n, q.w) * rn;
                }
                float3 phi = f3(factor * q.x, factor * q.y, factor * q.z);

                // jl_inv
                float t2 = dot3(phi, phi);
                bool sm2 = t2 < 1e-12f;
                float t2s = sm2 ? 1.0f : t2;
                float rth = rsqrtf(t2s);
                float theta = t2s * rth;
                float s, cth;
                __sincosf(theta, &s, &cth);
                float s_safe = (fabsf(s) < 1e-6f) ? 1e-6f : s;
                float c;
                if (sm2) {
                    c = (1.0f / 12.0f) + t2 * (1.0f / 720.0f);
                } else {
                    c = rth * rth - __fdividef(1.0f + cth, 2.0f * theta * s_safe);
                }
                float3 x1 = cross3(phi, t);
                float3 x2 = cross3(phi, x1);
                float3 tau = f3(t.x - 0.5f * x1.x + c * x2.x,
                                t.y - 0.5f * x1.y + c * x2.y,
                                t.z - 0.5f * x1.z + c * x2.z);

                float nd2 = dot3(phi, phi);
                if (nd2 < 1e-24f) {
                    o[0] = make_float4(tau.x, tau.y, tau.z, 0.f);
                    o[1] = make_float4(0.f, 0.f, 0.f, 0.f);
                    o[2] = make_float4(0.f, 0.f, 0.f, 0.f);
                    o[3] = make_float4(0.f, t0.x, t0.y, t0.z);
                } else {
                    float rnd = rsqrtf(nd2);
                    float nd  = nd2 * rnd;
                    float K2  = 2.0f * rnd * rnd;
                    float rn3 = rnd * rnd * rnd;
                    float3 U  = f3(phi.x * rnd, phi.y * rnd, phi.z * rnd);
                    float3 C1 = cross3(phi, tau);
                    float3 C2 = cross3(phi, C1);
                    C1.x *= K2;  C1.y *= K2;  C1.z *= K2;
                    C2.x *= rn3; C2.y *= rn3; C2.z *= rn3;
                    o[0] = make_float4(tau.x, tau.y, tau.z, nd);
                    o[1] = make_float4(U.x, U.y, U.z, C1.x);
                    o[2] = make_float4(C1.y, C1.z, C2.x, C2.y);
                    o[3] = make_float4(C2.z, t0.x, t0.y, t0.z);
                }
            }
        }
    }

    // per-lane weights (independent of phase 1 -> before the barrier)
    const unsigned w    = tid >> 5;
    const unsigned lane = tid & 31;
    float u  = __ldg(timev + lane);
    float u2 = u * u;
    float u3 = u2 * u;
    const float w0 = (5.0f + 3.0f * u - 3.0f * u2 + u3) * (1.0f / 6.0f);
    const float w1 = (1.0f + 3.0f * u + 3.0f * u2 - 2.0f * u3) * (1.0f / 6.0f);
    const float w2 = u3 * (1.0f / 6.0f);

    __syncthreads();

    // ---------------- Phase 2: 4 interleaved compose chains -----------------
    const unsigned s0 = s_base + 4 * w;
    unsigned nvalid = LS_S - s0;          // >= 1 always (s0 <= 2044)
    if (nvalid > 4) nvalid = 4;

    const float4* R = rec + (4 * w) * 5;  // warp-uniform smem

    Xf T0, T1, T2, T3;
    {
        float4 r0 = R[0], r1 = R[1], r2 = R[2], r3 = R[3], r4 = R[4];
        T0.t = f3(r3.y, r3.z, r3.w);  T0.q = r4;
        stepc(T0, r0, r1, r2, r3.x, w0);
    }
    {
        const float4* Rr = R + 5;
        float4 r0 = Rr[0], r1 = Rr[1], r2 = Rr[2], r3 = Rr[3], r4 = Rr[4];
        T1.t = f3(r3.y, r3.z, r3.w);  T1.q = r4;
        stepc(T1, r0, r1, r2, r3.x, w0);
        stepc(T0, r0, r1, r2, r3.x, w1);
    }
    {
        const float4* Rr = R + 10;
        float4 r0 = Rr[0], r1 = Rr[1], r2 = Rr[2], r3 = Rr[3], r4 = Rr[4];
        T2.t = f3(r3.y, r3.z, r3.w);  T2.q = r4;
        stepc(T2, r0, r1, r2, r3.x, w0);
        stepc(T1, r0, r1, r2, r3.x, w1);
        stepc(T0, r0, r1, r2, r3.x, w2);
    }
    {
        const float4* Rr = R + 15;
        float4 r0 = Rr[0], r1 = Rr[1], r2 = Rr[2], r3 = Rr[3], r4 = Rr[4];
        T3.t = f3(r3.y, r3.z, r3.w);  T3.q = r4;
        stepc(T3, r0, r1, r2, r3.x, w0);
        stepc(T2, r0, r1, r2, r3.x, w1);
        stepc(T1, r0, r1, r2, r3.x, w2);
    }
    {
        const float4* Rr = R + 20;
        float4 r0 = Rr[0], r1 = Rr[1], r2 = Rr[2];
        float c2z = Rr[3].x;
        stepc(T3, r0, r1, r2, c2z, w1);
        stepc(T2, r0, r1, r2, c2z, w2);
    }
    {
        const float4* Rr = R + 25;
        float4 r0 = Rr[0], r1 = Rr[1], r2 = Rr[2];
        float c2z = Rr[3].x;
        stepc(T3, r0, r1, r2, c2z, w2);
    }

    // stage through shared; 896 contiguous floats per warp
    float* smw = stg + w * 896;
    unsigned o7 = lane * 7;
    {
        float* p = smw + o7;
        p[0] = T0.t.x; p[1] = T0.t.y; p[2] = T0.t.z;
        p[3] = T0.q.x; p[4] = T0.q.y; p[5] = T0.q.z; p[6] = T0.q.w;
        p += 224;
        p[0] = T1.t.x; p[1] = T1.t.y; p[2] = T1.t.z;
        p[3] = T1.q.x; p[4] = T1.q.y; p[5] = T1.q.z; p[6] = T1.q.w;
        p += 224;
        p[0] = T2.t.x; p[1] = T2.t.y; p[2] = T2.t.z;
        p[3] = T2.q.x; p[4] = T2.q.y; p[5] = T2.q.z; p[6] = T2.q.w;
        p += 224;
        p[0] = T3.t.x; p[1] = T3.t.y; p[2] = T3.t.z;
        p[3] = T3.q.x; p[4] = T3.q.y; p[5] = T3.q.z; p[6] = T3.q.w;
    }
    __syncwarp();

    const float4* sm4 = (const float4*)smw;
    unsigned pair0 = b * LS_S + s0;
    float4* ob4 = (float4*)(out) + pair0 * 56;   // 224 floats = 56 float4
    unsigned nf4 = nvalid * 56;                  // 224 (full) or 168 (tail)
#pragma unroll 7
    for (unsigned i = lane; i < nf4; i += 32)
        ob4[i] = sm4[i];
}

extern "C" void kernel_launch(void* const* d_in, const int* in_sizes, int n_in,
                              void* d_out, int out_size) {
    (void)n_in; (void)out_size;
    const float* poses = (const float*)d_in[0];
    const float* timev = (const float*)d_in[1];
    float* out = (float*)d_out;

    dim3 grid(BLK_PER_B, LS_B);
    k_fused<<<grid, 256>>>(poses, timev, out);
}